// round 2
// baseline (speedup 1.0000x reference)
#include <cuda_runtime.h>

#define DECAY 0.99f
#define OMD   0.01f      /* 1 - DECAY */
#define EPS   1e-5f
#define NROWS 32768
#define DDIM  128
#define KCODES 1024
#define BM 64
#define BN 64
#define THREADS 256

// scratch (no device mallocs allowed)
__device__ float g_e2[KCODES];
__device__ int   g_idx[NROWS];
__device__ float g_sm[KCODES];

// ---------------------------------------------------------------------------
// ||e||^2 per code: one warp per code, one float4 per lane (32*4 = 128 dims)
// ---------------------------------------------------------------------------
__global__ void e2_kernel(const float* __restrict__ embed) {
    int warp = (blockIdx.x * blockDim.x + threadIdx.x) >> 5;
    int lane = threadIdx.x & 31;
    if (warp >= KCODES) return;
    float4 a = *((const float4*)(embed + (size_t)warp * DDIM) + lane);
    float s = a.x * a.x + a.y * a.y + a.z * a.z + a.w * a.w;
    #pragma unroll
    for (int o = 16; o; o >>= 1) s += __shfl_xor_sync(0xffffffffu, s, o);
    if (lane == 0) g_e2[warp] = s;
}

// ---------------------------------------------------------------------------
// Fused distance GEMM + argmax.
// dist(n,k) (up to row-constant) = 2 * x_n . e_k - ||e_k||^2
// Tiling: BM=64 rows per block (x tile in smem, transposed), loop over 16
// tiles of BN=64 codes. 256 threads, 4x4 register micro-tile.
// ---------------------------------------------------------------------------
__global__ void __launch_bounds__(THREADS)
dist_argmax_kernel(const float* __restrict__ x,
                   const float* __restrict__ embed,
                   float* __restrict__ out_ind) {
    extern __shared__ float smem[];
    float* xs = smem;               // [DDIM][BM]
    float* es = smem + DDIM * BM;   // [DDIM][BN]

    const int tid = threadIdx.x;
    const int tx = tid & 15;        // code dim (16 groups of 4 codes)
    const int ty = tid >> 4;        // row dim  (16 groups of 4 rows)
    const int row0 = blockIdx.x * BM;

    // Load x tile transposed: xs[d][row]. Lanes write consecutive rows
    // (conflict-free STS); gmem gathers 16B per lane (x read once total).
    for (int i = tid; i < BM * (DDIM / 4); i += THREADS) {
        int row = i & (BM - 1);
        int d4  = i >> 6;           // / BM
        float4 v = *(const float4*)(x + (size_t)(row0 + row) * DDIM + d4 * 4);
        xs[(d4 * 4 + 0) * BM + row] = v.x;
        xs[(d4 * 4 + 1) * BM + row] = v.y;
        xs[(d4 * 4 + 2) * BM + row] = v.z;
        xs[(d4 * 4 + 3) * BM + row] = v.w;
    }

    float bv[4]; int bi[4];
    #pragma unroll
    for (int i = 0; i < 4; i++) { bv[i] = -3.4e38f; bi[i] = 0; }

    for (int kt = 0; kt < KCODES / BN; kt++) {
        __syncthreads();  // protect es from previous iteration's readers
        for (int i = tid; i < BN * (DDIM / 4); i += THREADS) {
            int kk = i & (BN - 1);
            int d4 = i >> 6;        // / BN
            float4 v = *(const float4*)(embed + (size_t)(kt * BN + kk) * DDIM + d4 * 4);
            es[(d4 * 4 + 0) * BN + kk] = v.x;
            es[(d4 * 4 + 1) * BN + kk] = v.y;
            es[(d4 * 4 + 2) * BN + kk] = v.z;
            es[(d4 * 4 + 3) * BN + kk] = v.w;
        }
        __syncthreads();

        float acc[4][4];
        #pragma unroll
        for (int i = 0; i < 4; i++)
            #pragma unroll
            for (int j = 0; j < 4; j++) acc[i][j] = 0.f;

        #pragma unroll 4
        for (int d = 0; d < DDIM; d++) {
            float4 xf = *(float4*)&xs[d * BM + ty * 4];
            float4 ef = *(float4*)&es[d * BN + tx * 4];
            float xr[4] = {xf.x, xf.y, xf.z, xf.w};
            float er[4] = {ef.x, ef.y, ef.z, ef.w};
            #pragma unroll
            for (int i = 0; i < 4; i++)
                #pragma unroll
                for (int j = 0; j < 4; j++)
                    acc[i][j] = fmaf(xr[i], er[j], acc[i][j]);
        }

        // Update running argmax. j ascending => k ascending per thread;
        // strict '>' keeps the FIRST maximum (jnp.argmax semantics).
        #pragma unroll
        for (int j = 0; j < 4; j++) {
            int k = kt * BN + tx * 4 + j;
            float e2 = g_e2[k];
            #pragma unroll
            for (int i = 0; i < 4; i++) {
                float v = 2.f * acc[i][j] - e2;
                if (v > bv[i]) { bv[i] = v; bi[i] = k; }
            }
        }
    }

    // Cross-thread reduction per row (16 candidates per row).
    __syncthreads();
    float* rv = smem;                       // [BM][16] (reuse xs region)
    int*   ri = (int*)(smem + DDIM * BM);   // [BM][16] (reuse es region)
    #pragma unroll
    for (int i = 0; i < 4; i++) {
        rv[(ty * 4 + i) * 16 + tx] = bv[i];
        ri[(ty * 4 + i) * 16 + tx] = bi[i];
    }
    __syncthreads();
    if (tid < BM) {
        float best = -3.4e38f; int bidx = 0x7fffffff;
        #pragma unroll
        for (int t = 0; t < 16; t++) {
            float v = rv[tid * 16 + t];
            int   k = ri[tid * 16 + t];
            if (v > best || (v == best && k < bidx)) { best = v; bidx = k; }
        }
        g_idx[row0 + tid] = bidx;
        out_ind[row0 + tid] = (float)bidx;
    }
}

// ---------------------------------------------------------------------------
// quantize[n] = embed[idx[n]] : one float4 per thread
// ---------------------------------------------------------------------------
__global__ void gather_kernel(const float* __restrict__ embed,
                              float* __restrict__ out_q) {
    int t = blockIdx.x * blockDim.x + threadIdx.x;   // NROWS*32 threads
    int n = t >> 5, c = t & 31;
    int k = g_idx[n];
    float4 v = *((const float4*)(embed + (size_t)k * DDIM) + c);
    *((float4*)(out_q + (size_t)n * DDIM) + c) = v;
}

// ---------------------------------------------------------------------------
// out_cs = cluster_size * DECAY ; out_avg = embed_avg * DECAY
// ---------------------------------------------------------------------------
__global__ void init_kernel(const float* __restrict__ cluster_size,
                            const float* __restrict__ embed_avg,
                            float* __restrict__ out_cs,
                            float* __restrict__ out_avg) {
    int i = blockIdx.x * blockDim.x + threadIdx.x;   // 32768 float4s
    float4 v = *((const float4*)embed_avg + i);
    v.x *= DECAY; v.y *= DECAY; v.z *= DECAY; v.w *= DECAY;
    *((float4*)out_avg + i) = v;
    if (i < KCODES) out_cs[i] = cluster_size[i] * DECAY;
}

// ---------------------------------------------------------------------------
// EMA scatter: warp per row. counts += 0.01, embed_avg[k] += 0.01 * x[n]
// ---------------------------------------------------------------------------
__global__ void scatter_kernel(const float* __restrict__ x,
                               float* __restrict__ out_cs,
                               float* __restrict__ out_avg) {
    int t = blockIdx.x * blockDim.x + threadIdx.x;   // NROWS*32 threads
    int n = t >> 5, lane = t & 31;
    int k = g_idx[n];
    float4 v = *((const float4*)(x + (size_t)n * DDIM) + lane);
    float* dst = out_avg + (size_t)k * DDIM + lane * 4;
    atomicAdd(dst + 0, OMD * v.x);
    atomicAdd(dst + 1, OMD * v.y);
    atomicAdd(dst + 2, OMD * v.z);
    atomicAdd(dst + 3, OMD * v.w);
    if (lane == 0) atomicAdd(out_cs + k, OMD);
}

// ---------------------------------------------------------------------------
// total = sum(new_cluster_size); smoothed[k] = (c+eps)/(total+K*eps)*total
// ---------------------------------------------------------------------------
__global__ void finalize1_kernel(const float* __restrict__ out_cs) {
    __shared__ float red[KCODES];
    int tid = threadIdx.x;
    float c = out_cs[tid];
    red[tid] = c;
    __syncthreads();
    for (int s = 512; s; s >>= 1) {
        if (tid < s) red[tid] += red[tid + s];
        __syncthreads();
    }
    float total = red[0];
    g_sm[tid] = (c + EPS) / (total + KCODES * EPS) * total;
}

__global__ void finalize2_kernel(const float* __restrict__ out_avg,
                                 float* __restrict__ out_ne) {
    int i = blockIdx.x * blockDim.x + threadIdx.x;   // 32768 float4s
    float sm = g_sm[i >> 5];
    float4 v = *((const float4*)out_avg + i);
    v.x /= sm; v.y /= sm; v.z /= sm; v.w /= sm;
    *((float4*)out_ne + i) = v;
}

// ---------------------------------------------------------------------------
extern "C" void kernel_launch(void* const* d_in, const int* in_sizes, int n_in,
                              void* d_out, int out_size) {
    const float* x            = (const float*)d_in[0];
    const float* embed        = (const float*)d_in[1];
    const float* cluster_size = (const float*)d_in[2];
    const float* embed_avg    = (const float*)d_in[3];

    float* out      = (float*)d_out;
    float* out_q    = out;                               // 32768*128
    float* out_ind  = out_q  + (size_t)NROWS * DDIM;     // 32768
    float* out_cs   = out_ind + NROWS;                   // 1024
    float* out_avg  = out_cs + KCODES;                   // 1024*128
    float* out_ne   = out_avg + (size_t)KCODES * DDIM;   // 1024*128

    cudaFuncSetAttribute(dist_argmax_kernel,
                         cudaFuncAttributeMaxDynamicSharedMemorySize,
                         2 * DDIM * BM * (int)sizeof(float));

    e2_kernel<<<KCODES * 32 / THREADS, THREADS>>>(embed);
    dist_argmax_kernel<<<NROWS / BM, THREADS, 2 * DDIM * BM * sizeof(float)>>>(
        x, embed, out_ind);
    gather_kernel<<<NROWS * 32 / THREADS, THREADS>>>(embed, out_q);
    init_kernel<<<KCODES * DDIM / 4 / THREADS, THREADS>>>(cluster_size, embed_avg,
                                                          out_cs, out_avg);
    scatter_kernel<<<NROWS * 32 / THREADS, THREADS>>>(x, out_cs, out_avg);
    finalize1_kernel<<<1, KCODES>>>(out_cs);
    finalize2_kernel<<<KCODES * DDIM / 4 / THREADS, THREADS>>>(out_avg, out_ne);
}

// round 3
// speedup vs baseline: 1.2052x; 1.2052x over previous
#include <cuda_runtime.h>

#define DECAY 0.99f
#define OMD   0.01f
#define EPS   1e-5f
#define NROWS 32768
#define DDIM  128
#define KCODES 1024
#define BM 128
#define BN 64
#define THREADS 256
#define ND2 (DDIM / 2)       /* 64 d-pairs */
#define NKT (KCODES / BN)    /* 16 code tiles */

typedef unsigned long long ull;

// scratch (no device mallocs allowed)
__device__ float g_e2[KCODES];
__device__ int   g_idx[NROWS];
__device__ float g_sm[KCODES];

// packed f32x2 FMA: {d.lo,d.hi} = {a.lo*b.lo+c.lo, a.hi*b.hi+c.hi}
__device__ __forceinline__ ull ffma2(ull a, ull b, ull c) {
    ull d;
    asm("fma.rn.f32x2 %0, %1, %2, %3;" : "=l"(d) : "l"(a), "l"(b), "l"(c));
    return d;
}

// ---------------------------------------------------------------------------
// ||e||^2 per code: one warp per code
// ---------------------------------------------------------------------------
__global__ void e2_kernel(const float* __restrict__ embed) {
    int warp = (blockIdx.x * blockDim.x + threadIdx.x) >> 5;
    int lane = threadIdx.x & 31;
    if (warp >= KCODES) return;
    float4 a = *((const float4*)(embed + (size_t)warp * DDIM) + lane);
    float s = a.x * a.x + a.y * a.y + a.z * a.z + a.w * a.w;
    #pragma unroll
    for (int o = 16; o; o >>= 1) s += __shfl_xor_sync(0xffffffffu, s, o);
    if (lane == 0) g_e2[warp] = s;
}

// ---------------------------------------------------------------------------
// Fused distance GEMM + argmax using packed f32x2 FMA.
// Accumulator pair = {sum over even d, sum over odd d}; combined at tile end.
// BM=128 rows/CTA, BN=64 codes/tile (16 tiles), 256 threads, 8x4 microtile.
// smem: xs[ND2][BM] pairs (64KB) + es double buffer 2x[ND2][BN] (2x32KB).
// ---------------------------------------------------------------------------
__global__ void __launch_bounds__(THREADS)
dist_argmax_kernel(const float* __restrict__ x,
                   const float* __restrict__ embed,
                   float* __restrict__ out_ind) {
    extern __shared__ ull smem[];
    ull* xs = smem;                         // [ND2][BM]
    ull* es_buf0 = smem + ND2 * BM;         // [ND2][BN]
    ull* es_buf1 = es_buf0 + ND2 * BN;      // [ND2][BN]

    const int tid = threadIdx.x;
    const int tx = tid & 15;                // 16 groups of 4 codes
    const int ty = tid >> 4;                // 16 groups of 8 rows
    const int row0 = blockIdx.x * BM;

    // Load x tile as d-pairs, transposed: xs[d2][row].
    // row = i&127 -> consecutive lanes write consecutive rows (STS conflict-free)
    for (int i = tid; i < BM * (DDIM / 4); i += THREADS) {
        int row = i & (BM - 1);
        int d4  = i >> 7;
        float4 v = *(const float4*)(x + (size_t)(row0 + row) * DDIM + d4 * 4);
        xs[(d4 * 2 + 0) * BM + row] = ((const ull*)&v)[0];
        xs[(d4 * 2 + 1) * BM + row] = ((const ull*)&v)[1];
    }

    // Preload es tile kt=0
    for (int i = tid; i < BN * (DDIM / 4); i += THREADS) {
        int code = i & (BN - 1);
        int d4   = i >> 6;
        float4 v = *(const float4*)(embed + (size_t)code * DDIM + d4 * 4);
        es_buf0[(d4 * 2 + 0) * BN + code] = ((const ull*)&v)[0];
        es_buf0[(d4 * 2 + 1) * BN + code] = ((const ull*)&v)[1];
    }
    __syncthreads();

    float bv[8]; int bi[8];
    #pragma unroll
    for (int i = 0; i < 8; i++) { bv[i] = -3.4e38f; bi[i] = 0; }

    float4 pf[8];  // register staging for next es tile (8 float4/thread = 32KB/CTA)

    for (int kt = 0; kt < NKT; kt++) {
        const ull* es = (kt & 1) ? es_buf1 : es_buf0;
        ull*       nb = (kt & 1) ? es_buf0 : es_buf1;

        // Issue prefetch loads for next tile (latency hidden by compute)
        if (kt + 1 < NKT) {
            #pragma unroll
            for (int r = 0; r < 8; r++) {
                int i    = tid + r * THREADS;
                int code = i & (BN - 1);
                int d4   = i >> 6;
                pf[r] = *(const float4*)(embed +
                        (size_t)((kt + 1) * BN + code) * DDIM + d4 * 4);
            }
        }

        ull acc[8][4];
        #pragma unroll
        for (int i = 0; i < 8; i++)
            #pragma unroll
            for (int j = 0; j < 4; j++) acc[i][j] = 0ULL;

        #pragma unroll 2
        for (int d2 = 0; d2 < ND2; d2++) {
            ull x2[8], e2[4];
            {
                ulonglong2 p;
                p = *(const ulonglong2*)&xs[d2 * BM + ty * 8 + 0]; x2[0]=p.x; x2[1]=p.y;
                p = *(const ulonglong2*)&xs[d2 * BM + ty * 8 + 2]; x2[2]=p.x; x2[3]=p.y;
                p = *(const ulonglong2*)&xs[d2 * BM + ty * 8 + 4]; x2[4]=p.x; x2[5]=p.y;
                p = *(const ulonglong2*)&xs[d2 * BM + ty * 8 + 6]; x2[6]=p.x; x2[7]=p.y;
                p = *(const ulonglong2*)&es[d2 * BN + tx * 4 + 0]; e2[0]=p.x; e2[1]=p.y;
                p = *(const ulonglong2*)&es[d2 * BN + tx * 4 + 2]; e2[2]=p.x; e2[3]=p.y;
            }
            #pragma unroll
            for (int i = 0; i < 8; i++)
                #pragma unroll
                for (int j = 0; j < 4; j++)
                    acc[i][j] = ffma2(x2[i], e2[j], acc[i][j]);
        }

        // Argmax update. k ascending per thread across kt/j; strict '>'
        // keeps the FIRST maximum (jnp.argmax semantics).
        #pragma unroll
        for (int j = 0; j < 4; j++) {
            int k = kt * BN + tx * 4 + j;
            float e2k = g_e2[k];
            #pragma unroll
            for (int i = 0; i < 8; i++) {
                float2 f = *(float2*)&acc[i][j];
                float v = 2.f * (f.x + f.y) - e2k;
                if (v > bv[i]) { bv[i] = v; bi[i] = k; }
            }
        }

        // Commit prefetched tile to the other buffer
        if (kt + 1 < NKT) {
            __syncthreads();   // all readers of nb (from kt-1) are done
            #pragma unroll
            for (int r = 0; r < 8; r++) {
                int i    = tid + r * THREADS;
                int code = i & (BN - 1);
                int d4   = i >> 6;
                nb[(d4 * 2 + 0) * BN + code] = ((const ull*)&pf[r])[0];
                nb[(d4 * 2 + 1) * BN + code] = ((const ull*)&pf[r])[1];
            }
            __syncthreads();   // tile visible for next iteration
        }
    }

    // Cross-thread reduction: 16 candidates per row.
    __syncthreads();
    float* rv = (float*)smem;                 // [BM][16]
    int*   ri = (int*)smem + BM * 16;         // [BM][16]
    #pragma unroll
    for (int i = 0; i < 8; i++) {
        rv[(ty * 8 + i) * 16 + tx] = bv[i];
        ri[(ty * 8 + i) * 16 + tx] = bi[i];
    }
    __syncthreads();
    if (tid < BM) {
        float best = -3.4e38f; int bidx = 0x7fffffff;
        #pragma unroll
        for (int t = 0; t < 16; t++) {
            float v = rv[tid * 16 + t];
            int   k = ri[tid * 16 + t];
            if (v > best || (v == best && k < bidx)) { best = v; bidx = k; }
        }
        g_idx[row0 + tid] = bidx;
        out_ind[row0 + tid] = (float)bidx;
    }
}

// ---------------------------------------------------------------------------
// quantize[n] = embed[idx[n]]
// ---------------------------------------------------------------------------
__global__ void gather_kernel(const float* __restrict__ embed,
                              float* __restrict__ out_q) {
    int t = blockIdx.x * blockDim.x + threadIdx.x;   // NROWS*32 threads
    int n = t >> 5, c = t & 31;
    int k = g_idx[n];
    float4 v = *((const float4*)(embed + (size_t)k * DDIM) + c);
    *((float4*)(out_q + (size_t)n * DDIM) + c) = v;
}

// ---------------------------------------------------------------------------
// out_cs = cluster_size * DECAY ; out_avg = embed_avg * DECAY
// ---------------------------------------------------------------------------
__global__ void init_kernel(const float* __restrict__ cluster_size,
                            const float* __restrict__ embed_avg,
                            float* __restrict__ out_cs,
                            float* __restrict__ out_avg) {
    int i = blockIdx.x * blockDim.x + threadIdx.x;   // 32768 float4s
    float4 v = *((const float4*)embed_avg + i);
    v.x *= DECAY; v.y *= DECAY; v.z *= DECAY; v.w *= DECAY;
    *((float4*)out_avg + i) = v;
    if (i < KCODES) out_cs[i] = cluster_size[i] * DECAY;
}

// ---------------------------------------------------------------------------
// EMA scatter: warp per row
// ---------------------------------------------------------------------------
__global__ void scatter_kernel(const float* __restrict__ x,
                               float* __restrict__ out_cs,
                               float* __restrict__ out_avg) {
    int t = blockIdx.x * blockDim.x + threadIdx.x;   // NROWS*32 threads
    int n = t >> 5, lane = t & 31;
    int k = g_idx[n];
    float4 v = *((const float4*)(x + (size_t)n * DDIM) + lane);
    float* dst = out_avg + (size_t)k * DDIM + lane * 4;
    atomicAdd(dst + 0, OMD * v.x);
    atomicAdd(dst + 1, OMD * v.y);
    atomicAdd(dst + 2, OMD * v.z);
    atomicAdd(dst + 3, OMD * v.w);
    if (lane == 0) atomicAdd(out_cs + k, OMD);
}

// ---------------------------------------------------------------------------
// smoothed normalize
// ---------------------------------------------------------------------------
__global__ void finalize1_kernel(const float* __restrict__ out_cs) {
    __shared__ float red[KCODES];
    int tid = threadIdx.x;
    float c = out_cs[tid];
    red[tid] = c;
    __syncthreads();
    for (int s = 512; s; s >>= 1) {
        if (tid < s) red[tid] += red[tid + s];
        __syncthreads();
    }
    float total = red[0];
    g_sm[tid] = (c + EPS) / (total + KCODES * EPS) * total;
}

__global__ void finalize2_kernel(const float* __restrict__ out_avg,
                                 float* __restrict__ out_ne) {
    int i = blockIdx.x * blockDim.x + threadIdx.x;   // 32768 float4s
    float sm = g_sm[i >> 5];
    float4 v = *((const float4*)out_avg + i);
    v.x /= sm; v.y /= sm; v.z /= sm; v.w /= sm;
    *((float4*)out_ne + i) = v;
}

// ---------------------------------------------------------------------------
extern "C" void kernel_launch(void* const* d_in, const int* in_sizes, int n_in,
                              void* d_out, int out_size) {
    const float* x            = (const float*)d_in[0];
    const float* embed        = (const float*)d_in[1];
    const float* cluster_size = (const float*)d_in[2];
    const float* embed_avg    = (const float*)d_in[3];

    float* out      = (float*)d_out;
    float* out_q    = out;                               // 32768*128
    float* out_ind  = out_q  + (size_t)NROWS * DDIM;     // 32768
    float* out_cs   = out_ind + NROWS;                   // 1024
    float* out_avg  = out_cs + KCODES;                   // 1024*128
    float* out_ne   = out_avg + (size_t)KCODES * DDIM;   // 1024*128

    const int smem_bytes = (ND2 * BM + 2 * ND2 * BN) * (int)sizeof(ull); // 128KB
    cudaFuncSetAttribute(dist_argmax_kernel,
                         cudaFuncAttributeMaxDynamicSharedMemorySize, smem_bytes);

    e2_kernel<<<KCODES * 32 / THREADS, THREADS>>>(embed);
    dist_argmax_kernel<<<NROWS / BM, THREADS, smem_bytes>>>(x, embed, out_ind);
    gather_kernel<<<NROWS * 32 / THREADS, THREADS>>>(embed, out_q);
    init_kernel<<<KCODES * DDIM / 4 / THREADS, THREADS>>>(cluster_size, embed_avg,
                                                          out_cs, out_avg);
    scatter_kernel<<<NROWS * 32 / THREADS, THREADS>>>(x, out_cs, out_avg);
    finalize1_kernel<<<1, KCODES>>>(out_cs);
    finalize2_kernel<<<KCODES * DDIM / 4 / THREADS, THREADS>>>(out_avg, out_ne);
}

// round 5
// speedup vs baseline: 1.4793x; 1.2274x over previous
#include <cuda_runtime.h>
#include <cuda_bf16.h>
#include <stdint.h>
#include <float.h>

#define DECAY 0.99f
#define OMD   0.01f
#define EPS   1e-5f
#define NROWS 32768
#define DDIM  128
#define KCODES 1024
#define THREADS 256
#define BM 128                   /* rows per CTA  */
#define BN 128                   /* codes per tile */
#define NBLK (KCODES / BN)       /* 8 */
#define MARGIN 0.008f

/* smem byte offsets */
#define OFF_X1   0               /* 128x128 bf16 swizzled, 32KB */
#define OFF_X2   32768
#define OFF_E0   65536           /* buf0: e1 (32KB) + e2 (32KB) */
#define OFF_E1   131072          /* buf1 */
#define OFF_ES2  196608          /* es2[2][128] floats */
#define SMEM_TOTAL (196608 + 1024)

typedef unsigned long long ull;

/* scratch (no device mallocs allowed) */
__device__ float         g_e2[KCODES];
__device__ int           g_idx[NROWS];
__device__ float         g_sm[KCODES];
__device__ __nv_bfloat16 g_eb1[KCODES * DDIM];
__device__ __nv_bfloat16 g_eb2[KCODES * DDIM];
__device__ unsigned char g_flag[NROWS];

/* ------------------------------------------------------------------ */
__device__ __forceinline__ uint32_t smem_u32(const void* p) {
    uint32_t a;
    asm("{ .reg .u64 t; cvta.to.shared.u64 t, %1; cvt.u32.u64 %0, t; }"
        : "=r"(a) : "l"(p));
    return a;
}
__device__ __forceinline__ uint32_t sw128(uint32_t off) {
    return off ^ ((off >> 3) & 0x70);
}
/* blocked SW128 atom layout for [128 rows x 128 bf16] K-major tile */
__device__ __forceinline__ uint32_t blk_off(int r, int c) {
    return ((uint32_t)((c >> 6) * 16 + (r >> 3)) << 10)
         + ((uint32_t)(r & 7) << 7) + ((uint32_t)(c & 63) << 1);
}
__device__ __forceinline__ uint32_t pack_bf(__nv_bfloat16 lo, __nv_bfloat16 hi) {
    uint16_t l = *reinterpret_cast<uint16_t*>(&lo);
    uint16_t h = *reinterpret_cast<uint16_t*>(&hi);
    return ((uint32_t)h << 16) | l;
}
__device__ __forceinline__ void ldsm4(uint32_t* r, uint32_t addr) {
    asm volatile("ldmatrix.sync.aligned.m8n8.x4.shared.b16 {%0,%1,%2,%3}, [%4];"
                 : "=r"(r[0]), "=r"(r[1]), "=r"(r[2]), "=r"(r[3]) : "r"(addr));
}
__device__ __forceinline__ void mma16816(float* d, const uint32_t* a,
                                         uint32_t b0, uint32_t b1) {
    asm volatile(
        "mma.sync.aligned.m16n8k16.row.col.f32.bf16.bf16.f32 "
        "{%0,%1,%2,%3}, {%4,%5,%6,%7}, {%8,%9}, {%0,%1,%2,%3};"
        : "+f"(d[0]), "+f"(d[1]), "+f"(d[2]), "+f"(d[3])
        : "r"(a[0]), "r"(a[1]), "r"(a[2]), "r"(a[3]), "r"(b0), "r"(b1));
}
#define CP16(dst, src) \
    asm volatile("cp.async.cg.shared.global [%0], [%1], 16;" \
                 :: "r"(dst), "l"(src) : "memory")
#define CP_COMMIT() asm volatile("cp.async.commit_group;" ::: "memory")
#define CP_WAIT(n)  asm volatile("cp.async.wait_group %0;" :: "n"(n) : "memory")

/* ------------------------------------------------------------------ */
/* embed prep: bf16 split + ||e||^2. one warp per code.                */
/* ------------------------------------------------------------------ */
__global__ void e_split_kernel(const float* __restrict__ embed) {
    int code = (blockIdx.x * blockDim.x + threadIdx.x) >> 5;
    int lane = threadIdx.x & 31;
    if (code >= KCODES) return;
    float4 a = *((const float4*)(embed + (size_t)code * DDIM) + lane);
    float f[4] = {a.x, a.y, a.z, a.w};
    __nv_bfloat16 b1[4], b2[4];
    float s = 0.f;
    #pragma unroll
    for (int j = 0; j < 4; j++) {
        s += f[j] * f[j];
        b1[j] = __float2bfloat16_rn(f[j]);
        float r = f[j] - __bfloat162float(b1[j]);
        b2[j] = __float2bfloat16_rn(r);
    }
    uint32_t* d1 = (uint32_t*)(g_eb1 + (size_t)code * DDIM + lane * 4);
    uint32_t* d2 = (uint32_t*)(g_eb2 + (size_t)code * DDIM + lane * 4);
    d1[0] = pack_bf(b1[0], b1[1]); d1[1] = pack_bf(b1[2], b1[3]);
    d2[0] = pack_bf(b2[0], b2[1]); d2[1] = pack_bf(b2[2], b2[3]);
    #pragma unroll
    for (int o = 16; o; o >>= 1) s += __shfl_xor_sync(0xffffffffu, s, o);
    if (lane == 0) g_e2[code] = s;
}

/* ------------------------------------------------------------------ */
/* mma.sync distance + approx argmax with top-2 margin flag            */
/* ------------------------------------------------------------------ */
__global__ void __launch_bounds__(THREADS)
dist_mma_kernel(const float* __restrict__ x, float* __restrict__ out_ind) {
    extern __shared__ char smem[];
    const uint32_t sb = smem_u32(smem);
    const int tid  = threadIdx.x;
    const int wid  = tid >> 5, lane = tid & 31;
    const int wr   = wid & 3, wc = wid >> 2;      /* warp grid 4x2 */
    const int gid  = lane >> 2, tig = lane & 3;
    const int lrow = lane & 15, lcol = (lane >> 4) << 3;
    const int row0 = blockIdx.x * BM;
    float* es2 = (float*)(smem + OFF_ES2);        /* [2][128] */

    /* x tile: split to bf16 pair, store swizzled */
    #pragma unroll
    for (int it = 0; it < 8; it++) {
        int i = tid + it * THREADS;
        int row = i >> 4, c8 = i & 15;
        const float* xp = x + (size_t)(row0 + row) * DDIM + c8 * 8;
        float4 fa = *(const float4*)xp;
        float4 fb = *(const float4*)(xp + 4);
        float f[8] = {fa.x, fa.y, fa.z, fa.w, fb.x, fb.y, fb.z, fb.w};
        uint32_t u1[4], u2[4];
        #pragma unroll
        for (int j = 0; j < 4; j++) {
            __nv_bfloat16 h0 = __float2bfloat16_rn(f[2*j]);
            __nv_bfloat16 h1 = __float2bfloat16_rn(f[2*j+1]);
            float r0 = f[2*j]   - __bfloat162float(h0);
            float r1 = f[2*j+1] - __bfloat162float(h1);
            u1[j] = pack_bf(h0, h1);
            u2[j] = pack_bf(__float2bfloat16_rn(r0), __float2bfloat16_rn(r1));
        }
        uint32_t off = sw128(blk_off(row, c8 * 8));
        *(uint4*)(smem + OFF_X1 + off) = make_uint4(u1[0], u1[1], u1[2], u1[3]);
        *(uint4*)(smem + OFF_X2 + off) = make_uint4(u2[0], u2[1], u2[2], u2[3]);
    }

    /* prologue: async-load e tile 0 into buf0 */
    #pragma unroll
    for (int r = 0; r < 8; r++) {
        int i = tid + r * THREADS;
        int row = i >> 4, c8 = i & 15;
        uint32_t off = sw128(blk_off(row, c8 * 8));
        const char* s1 = (const char*)(g_eb1 + (size_t)row * DDIM + c8 * 8);
        const char* s2 = (const char*)(g_eb2 + (size_t)row * DDIM + c8 * 8);
        CP16(sb + OFF_E0 + off, s1);
        CP16(sb + OFF_E0 + 32768 + off, s2);
    }
    if (tid < BN) es2[tid] = g_e2[tid];
    CP_COMMIT();

    float m1[4], m2[4]; int i1[4];
    #pragma unroll
    for (int r = 0; r < 4; r++) { m1[r] = -FLT_MAX; m2[r] = -FLT_MAX; i1[r] = 0; }

    for (int b = 0; b < NBLK; b++) {
        __syncthreads();   /* prev-iter readers of next buffer done */
        if (b + 1 < NBLK) {
            uint32_t eb = sb + ((b + 1) & 1 ? OFF_E1 : OFF_E0);
            #pragma unroll
            for (int r = 0; r < 8; r++) {
                int i = tid + r * THREADS;
                int row = i >> 4, c8 = i & 15;
                uint32_t off = sw128(blk_off(row, c8 * 8));
                size_t g = (size_t)((b + 1) * BN + row) * DDIM + c8 * 8;
                CP16(eb + off, (const char*)(g_eb1 + g));
                CP16(eb + 32768 + off, (const char*)(g_eb2 + g));
            }
            if (tid < BN) es2[((b + 1) & 1) * BN + tid] = g_e2[(b + 1) * BN + tid];
            CP_COMMIT();
            CP_WAIT(1);
        } else {
            CP_WAIT(0);
        }
        __syncthreads();   /* buffer b + es2[b] visible */

        const uint32_t e1b = sb + (b & 1 ? OFF_E1 : OFF_E0);
        const uint32_t e2b = e1b + 32768;
        const float* es2c = es2 + (b & 1) * BN;

        float acc[2][8][4];
        #pragma unroll
        for (int m = 0; m < 2; m++)
            #pragma unroll
            for (int j = 0; j < 8; j++)
                #pragma unroll
                for (int c = 0; c < 4; c++) acc[m][j][c] = 0.f;

        #pragma unroll
        for (int s = 0; s < 8; s++) {
            int k0 = s * 16;
            uint32_t a1[2][4], a2[2][4], q1[4][4], q2[4][4];
            #pragma unroll
            for (int m = 0; m < 2; m++) {
                uint32_t off = sw128(blk_off(wr * 32 + m * 16 + lrow, k0 + lcol));
                ldsm4(a1[m], sb + OFF_X1 + off);
                ldsm4(a2[m], sb + OFF_X2 + off);
            }
            #pragma unroll
            for (int t = 0; t < 4; t++) {
                uint32_t off = sw128(blk_off(wc * 64 + t * 16 + lrow, k0 + lcol));
                ldsm4(q1[t], e1b + off);
                ldsm4(q2[t], e2b + off);
            }
            #pragma unroll
            for (int m = 0; m < 2; m++)
                #pragma unroll
                for (int j = 0; j < 8; j++) {
                    int t = j >> 1, h = j & 1;
                    mma16816(acc[m][j], a1[m], q1[t][h], q1[t][h + 2]);
                    mma16816(acc[m][j], a1[m], q2[t][h], q2[t][h + 2]);
                    mma16816(acc[m][j], a2[m], q1[t][h], q1[t][h + 2]);
                }
        }

        /* argmax epilogue: k ascending per (lane,row) => strict '>' = first max */
        #pragma unroll
        for (int m = 0; m < 2; m++)
            #pragma unroll
            for (int j = 0; j < 8; j++) {
                int col = wc * 64 + j * 8 + tig * 2;
                float2 ee = *(const float2*)(es2c + col);
                int k = b * BN + col;
                #pragma unroll
                for (int h = 0; h < 2; h++) {
                    int r4 = m * 2 + h;
                    float v0 = fmaf(2.f, acc[m][j][h * 2 + 0], -ee.x);
                    float v1 = fmaf(2.f, acc[m][j][h * 2 + 1], -ee.y);
                    if (v0 > m1[r4]) { m2[r4] = m1[r4]; m1[r4] = v0; i1[r4] = k; }
                    else if (v0 > m2[r4]) m2[r4] = v0;
                    if (v1 > m1[r4]) { m2[r4] = m1[r4]; m1[r4] = v1; i1[r4] = k + 1; }
                    else if (v1 > m2[r4]) m2[r4] = v1;
                }
            }
    }

    /* cross-lane / cross-warp reduction via smem (reuse e buffers) */
    __syncthreads();
    float* red_m1 = (float*)(smem + OFF_E0);            /* [128][8] */
    float* red_m2 = red_m1 + BM * 8;
    int*   red_i1 = (int*)(red_m2 + BM * 8);
    #pragma unroll
    for (int r4 = 0; r4 < 4; r4++) {
        int row = wr * 32 + (r4 >> 1) * 16 + (r4 & 1) * 8 + gid;
        int slot = wc * 4 + tig;
        red_m1[row * 8 + slot] = m1[r4];
        red_m2[row * 8 + slot] = m2[r4];
        red_i1[row * 8 + slot] = i1[r4];
    }
    __syncthreads();
    if (tid < BM) {
        float bm1 = -FLT_MAX, bm2 = -FLT_MAX; int bi = 0x7fffffff;
        #pragma unroll
        for (int s = 0; s < 8; s++) {
            float em1 = red_m1[tid * 8 + s];
            float em2 = red_m2[tid * 8 + s];
            int   ei  = red_i1[tid * 8 + s];
            if (em1 > bm1 || (em1 == bm1 && ei < bi)) {
                bm2 = fmaxf(bm1, em2); bm1 = em1; bi = ei;
            } else {
                bm2 = fmaxf(bm2, em1);
            }
        }
        int row = row0 + tid;
        g_idx[row]   = bi;
        out_ind[row] = (float)bi;
        g_flag[row]  = (bm1 - bm2 < MARGIN) ? 1 : 0;
    }
}

/* ------------------------------------------------------------------ */
/* exact fp32 rescue for flagged rows: one warp per row                */
/* ------------------------------------------------------------------ */
__global__ void fixer_kernel(const float* __restrict__ x,
                             const float* __restrict__ embed,
                             float* __restrict__ out_ind) {
    int w = (blockIdx.x * blockDim.x + threadIdx.x) >> 5;
    int lane = threadIdx.x & 31;
    if (w >= NROWS || !g_flag[w]) return;
    float4 xv = *((const float4*)(x + (size_t)w * DDIM) + lane);
    float best = -FLT_MAX; int bi = 0;
    for (int k = 0; k < KCODES; k++) {
        float4 ev = *((const float4*)(embed + (size_t)k * DDIM) + lane);
        float p = xv.x * ev.x + xv.y * ev.y + xv.z * ev.z + xv.w * ev.w;
        #pragma unroll
        for (int o = 16; o; o >>= 1) p += __shfl_xor_sync(0xffffffffu, p, o);
        float s = 2.f * p - g_e2[k];
        if (s > best) { best = s; bi = k; }   /* first max wins */
    }
    if (lane == 0) { g_idx[w] = bi; out_ind[w] = (float)bi; }
}

/* ------------------------------------------------------------------ */
/* epilogue kernels                                                    */
/* ------------------------------------------------------------------ */
__global__ void gather_kernel(const float* __restrict__ embed,
                              float* __restrict__ out_q) {
    int t = blockIdx.x * blockDim.x + threadIdx.x;
    int n = t >> 5, c = t & 31;
    int k = g_idx[n];
    float4 v = *((const float4*)(embed + (size_t)k * DDIM) + c);
    *((float4*)(out_q + (size_t)n * DDIM) + c) = v;
}

__global__ void init_kernel(const float* __restrict__ cluster_size,
                            const float* __restrict__ embed_avg,
                            float* __restrict__ out_cs,
                            float* __restrict__ out_avg) {
    int i = blockIdx.x * blockDim.x + threadIdx.x;
    float4 v = *((const float4*)embed_avg + i);
    v.x *= DECAY; v.y *= DECAY; v.z *= DECAY; v.w *= DECAY;
    *((float4*)out_avg + i) = v;
    if (i < KCODES) out_cs[i] = cluster_size[i] * DECAY;
}

__global__ void scatter_kernel(const float* __restrict__ x,
                               float* __restrict__ out_cs,
                               float* __restrict__ out_avg) {
    int t = blockIdx.x * blockDim.x + threadIdx.x;
    int n = t >> 5, lane = t & 31;
    int k = g_idx[n];
    float4 v = *((const float4*)(x + (size_t)n * DDIM) + lane);
    float* dst = out_avg + (size_t)k * DDIM + lane * 4;
    atomicAdd(dst + 0, OMD * v.x);
    atomicAdd(dst + 1, OMD * v.y);
    atomicAdd(dst + 2, OMD * v.z);
    atomicAdd(dst + 3, OMD * v.w);
    if (lane == 0) atomicAdd(out_cs + k, OMD);
}

__global__ void finalize1_kernel(const float* __restrict__ out_cs) {
    __shared__ float red[KCODES];
    int tid = threadIdx.x;
    float c = out_cs[tid];
    red[tid] = c;
    __syncthreads();
    for (int s = 512; s; s >>= 1) {
        if (tid < s) red[tid] += red[tid + s];
        __syncthreads();
    }
    float total = red[0];
    g_sm[tid] = (c + EPS) / (total + KCODES * EPS) * total;
}

__global__ void finalize2_kernel(const float* __restrict__ out_avg,
                                 float* __restrict__ out_ne) {
    int i = blockIdx.x * blockDim.x + threadIdx.x;
    float sm = g_sm[i >> 5];
    float4 v = *((const float4*)out_avg + i);
    v.x /= sm; v.y /= sm; v.z /= sm; v.w /= sm;
    *((float4*)out_ne + i) = v;
}

/* ------------------------------------------------------------------ */
extern "C" void kernel_launch(void* const* d_in, const int* in_sizes, int n_in,
                              void* d_out, int out_size) {
    const float* x            = (const float*)d_in[0];
    const float* embed        = (const float*)d_in[1];
    const float* cluster_size = (const float*)d_in[2];
    const float* embed_avg    = (const float*)d_in[3];

    float* out      = (float*)d_out;
    float* out_q    = out;                               /* 32768*128 */
    float* out_ind  = out_q  + (size_t)NROWS * DDIM;     /* 32768     */
    float* out_cs   = out_ind + NROWS;                   /* 1024      */
    float* out_avg  = out_cs + KCODES;                   /* 1024*128  */
    float* out_ne   = out_avg + (size_t)KCODES * DDIM;   /* 1024*128  */

    cudaFuncSetAttribute(dist_mma_kernel,
                         cudaFuncAttributeMaxDynamicSharedMemorySize, SMEM_TOTAL);

    e_split_kernel<<<KCODES * 32 / THREADS, THREADS>>>(embed);
    dist_mma_kernel<<<NROWS / BM, THREADS, SMEM_TOTAL>>>(x, out_ind);
    fixer_kernel<<<NROWS * 32 / THREADS, THREADS>>>(x, embed, out_ind);
    gather_kernel<<<NROWS * 32 / THREADS, THREADS>>>(embed, out_q);
    init_kernel<<<KCODES * DDIM / 4 / THREADS, THREADS>>>(cluster_size, embed_avg,
                                                          out_cs, out_avg);
    scatter_kernel<<<NROWS * 32 / THREADS, THREADS>>>(x, out_cs, out_avg);
    finalize1_kernel<<<1, KCODES>>>(out_cs);
    finalize2_kernel<<<KCODES * DDIM / 4 / THREADS, THREADS>>>(out_avg, out_ne);
}